// round 11
// baseline (speedup 1.0000x reference)
#include <cuda_runtime.h>
#include <cuda_bf16.h>
#include <cstdint>

// ============================================================================
// CAM via Gram restructuring, mma.sync bf16 hi/lo.
// R11: gram tiles split over 2 CTAs (z), 64 regs/thread -> 2 CTAs/SM.
// ============================================================================

#define NPIX   65536
#define JT     208
#define SPLITS 37
#define GCH    128    // gram pixels per chunk
#define GSTR   136    // gram smem row stride (bf16)
#define ASTR   216    // out A smem stride (bf16)
#define OXS    136    // out X smem stride (bf16)
#define OTN    128    // out pixels per CTA

__device__ float g_Gp[4 * SPLITS * JT * JT];
__device__ float g_G[4 * JT * JT];
__device__ float g_T2[4 * 193 * 64];
__device__ unsigned short g_Mhi[4 * 64 * JT];
__device__ unsigned short g_Mlo[4 * 64 * JT];

// ---------------------------------------------------------------------------
static __device__ __forceinline__ uint32_t smem_u32(const void* p) {
    uint32_t a;
    asm("{ .reg .u64 t; cvta.to.shared.u64 t, %1; cvt.u32.u64 %0, t; }"
        : "=r"(a) : "l"(p));
    return a;
}

#define MMA16816(d, a0, a1, a2, a3, b0, b1) \
    asm volatile("mma.sync.aligned.m16n8k16.row.col.f32.bf16.bf16.f32 " \
        "{%0,%1,%2,%3}, {%4,%5,%6,%7}, {%8,%9}, {%0,%1,%2,%3};" \
        : "+f"((d)[0]), "+f"((d)[1]), "+f"((d)[2]), "+f"((d)[3]) \
        : "r"(a0), "r"(a1), "r"(a2), "r"(a3), "r"(b0), "r"(b1))

#define LDSM_X2_T(r0, r1, addr) \
    asm volatile("ldmatrix.sync.aligned.m8n8.x2.trans.shared.b16 {%0,%1}, [%2];" \
        : "=r"(r0), "=r"(r1) : "r"(addr))

static __device__ __forceinline__ void split_bf16(float x, unsigned short& h,
                                                  unsigned short& lo) {
    __nv_bfloat16 hb = __float2bfloat16(x);
    __nv_bfloat16 lb = __float2bfloat16(x - __bfloat162float(hb));
    h = __bfloat16_as_ushort(hb);
    lo = __bfloat16_as_ushort(lb);
}

__global__ void cam_nop() {}

// ---------------------------------------------------------------------------
// kernel 1: split-K Gram, tiles halved across blockIdx.z, 2 CTAs/SM
// ---------------------------------------------------------------------------
#define GRAM_SMEM (2 * JT * GSTR * 2)

__global__ __launch_bounds__(512, 2)
void cam_gram_mma(const float* __restrict__ rgb,
                  const float* __restrict__ hsv,
                  const float* __restrict__ lab) {
    extern __shared__ __align__(16) __nv_bfloat16 gsm[];
    __nv_bfloat16* hiP = gsm;                 // [208][136]
    __nv_bfloat16* loP = gsm + JT * GSTR;

    const int tid = threadIdx.x;
    const int l = tid & 31;
    const int w = tid >> 5;       // 0..15
    const int split = blockIdx.x;
    const int b = blockIdx.y;
    const int z = blockIdx.z;     // tile half

    const float* bases[3] = {
        rgb + (size_t)b * 64 * NPIX,
        hsv + (size_t)b * 64 * NPIX,
        lab + (size_t)b * 64 * NPIX
    };

    // static rows 192..207 (row 192 hi = 1.0, else 0)
    for (int idx = tid; idx < 2 * 16 * 64; idx += 512) {
        const int pl = idx >> 10;
        const int r = (idx >> 6) & 15;
        const int q = idx & 63;
        uint32_t* p = (uint32_t*)((pl ? loP : hiP) + (192 + r) * GSTR);
        p[q] = (pl == 0 && r == 0) ? 0x3F803F80u : 0u;
    }

    // tiles [z*91, z*91+91) over the 182 upper-tri (16x8) tiles;
    // per warp: 6 tiles (w<11) or 5 tiles (w>=11): 11*6 + 5*5 = 91
    const int startL = (w < 11) ? 6 * w : 66 + 5 * (w - 11);
    const int cnt = (w < 11) ? 6 : 5;
    const int start = z * 91 + startL;
    int mtA[6], ntA[6];
    {
        int rem = start, mt = 0;
        while (mt < 13 && rem >= 26 - 2 * mt) { rem -= 26 - 2 * mt; mt++; }
        int nt = 2 * mt + rem;
#pragma unroll
        for (int t = 0; t < 6; t++) {
            if (mt >= 13) { mt = 12; nt = 25; }
            mtA[t] = mt; ntA[t] = nt;
            nt++;
            if (nt >= 26) { mt++; nt = 2 * mt; }
        }
    }

    float acc[6][4];
#pragma unroll
    for (int t = 0; t < 6; t++)
#pragma unroll
        for (int q = 0; q < 4; q++) acc[t][q] = 0.0f;

    for (int chunk = split; chunk < NPIX / GCH; chunk += SPLITS) {
        const int n0 = chunk * GCH;
        __syncthreads();
        // stage rows 0..191: fp32 -> hi/lo bf16 (128 px)
        for (int idx = tid; idx < 192 * 64; idx += 512) {
            const int j = idx >> 6;
            const int pq = idx & 63;
            const float2 v = *(const float2*)(bases[j >> 6] +
                                              (size_t)(j & 63) * NPIX + n0 + pq * 2);
            unsigned short h0, l0, h1, l1;
            split_bf16(v.x, h0, l0);
            split_bf16(v.y, h1, l1);
            ((uint32_t*)(hiP + j * GSTR))[pq] = (uint32_t)h0 | ((uint32_t)h1 << 16);
            ((uint32_t*)(loP + j * GSTR))[pq] = (uint32_t)l0 | ((uint32_t)l1 << 16);
        }
        __syncthreads();

#pragma unroll 1
        for (int ks = 0; ks < GCH / 16; ks++) {
            int prev = -1;
            uint32_t ah0 = 0, ah1 = 0, ah2 = 0, ah3 = 0;
            uint32_t al0 = 0, al1 = 0, al2 = 0, al3 = 0;
#pragma unroll
            for (int t = 0; t < 6; t++) {
                if (t < cnt) {
                    const int mt = mtA[t];
                    const int nt = ntA[t];
                    if (mt != prev) {
                        prev = mt;
                        const int arow = mt * 16 + (l >> 2);
                        const uint32_t* ph = (const uint32_t*)(hiP + arow * GSTR + ks * 16);
                        const uint32_t* ph8 = ph + 8 * (GSTR / 2);
                        ah0 = ph[l & 3];  ah2 = ph[(l & 3) + 4];
                        ah1 = ph8[l & 3]; ah3 = ph8[(l & 3) + 4];
                        const uint32_t* ql = (const uint32_t*)(loP + arow * GSTR + ks * 16);
                        const uint32_t* ql8 = ql + 8 * (GSTR / 2);
                        al0 = ql[l & 3];  al2 = ql[(l & 3) + 4];
                        al1 = ql8[l & 3]; al3 = ql8[(l & 3) + 4];
                    }
                    const int brow = nt * 8 + (l >> 2);
                    const uint32_t* pb = (const uint32_t*)(hiP + brow * GSTR + ks * 16);
                    const uint32_t bh0 = pb[l & 3], bh1 = pb[(l & 3) + 4];
                    const uint32_t* pbl = (const uint32_t*)(loP + brow * GSTR + ks * 16);
                    const uint32_t bl0 = pbl[l & 3], bl1 = pbl[(l & 3) + 4];
                    MMA16816(acc[t], ah0, ah1, ah2, ah3, bh0, bh1);
                    MMA16816(acc[t], ah0, ah1, ah2, ah3, bl0, bl1);
                    MMA16816(acc[t], al0, al1, al2, al3, bh0, bh1);
                }
            }
        }
    }

    float* gp = g_Gp + (size_t)(b * SPLITS + split) * JT * JT;
#pragma unroll
    for (int t = 0; t < 6; t++) {
        if (t < cnt) {
            const int i0 = mtA[t] * 16 + (l >> 2);
            const int j0 = ntA[t] * 8 + 2 * (l & 3);
            *(float2*)&gp[(size_t)i0 * JT + j0] = make_float2(acc[t][0], acc[t][1]);
            *(float2*)&gp[(size_t)(i0 + 8) * JT + j0] = make_float2(acc[t][2], acc[t][3]);
        }
    }
}

// ---------------------------------------------------------------------------
// kernel 2: reduce split-K + mirror
// ---------------------------------------------------------------------------
__global__ void cam_reduceG() {
    const int idx = blockIdx.x * 256 + threadIdx.x;
    const int b = idx / (JT * JT);
    const int rc = idx % (JT * JT);
    const int i = rc / JT, j = rc % JT;
    if (i > j) return;
    const float* gp = g_Gp + (size_t)b * SPLITS * JT * JT + rc;
    float acc = 0.0f;
#pragma unroll 4
    for (int s = 0; s < SPLITS; s++) acc += gp[(size_t)s * JT * JT];
    float* G = g_G + (size_t)b * JT * JT;
    G[i * JT + j] = acc;
    G[j * JT + i] = acc;
}

// ---------------------------------------------------------------------------
// kernel 3: T2[b][i][d] = sum_j G[b][i][j] Wk_aug[d][j]
// ---------------------------------------------------------------------------
__global__ void cam_projT2(const float* __restrict__ Wk,
                           const float* __restrict__ bk) {
    __shared__ float Gs[4][200];
    const int b = blockIdx.y;
    const int i0 = blockIdx.x * 4;
    const int tid = threadIdx.x;

    for (int idx = tid; idx < 4 * 193; idx += 256) {
        const int ii = idx / 193, j = idx % 193;
        if (i0 + ii < 193)
            Gs[ii][j] = g_G[(size_t)b * JT * JT + (size_t)(i0 + ii) * JT + j];
    }
    __syncthreads();

    const int d = tid & 63;
    const int ii = tid >> 6;
    const int i = i0 + ii;
    if (i < 193) {
        float acc = 0.0f;
#pragma unroll 4
        for (int j = 0; j < 192; j++) acc += Wk[d * 192 + j] * Gs[ii][j];
        acc += bk[d] * Gs[ii][192];
        g_T2[(size_t)b * 193 * 64 + i * 64 + d] = acc;
    }
}

// ---------------------------------------------------------------------------
// kernel 4: energy + softmax + M row, fused  (grid (64,4), 256 threads)
// ---------------------------------------------------------------------------
__global__ void cam_energyM(const float* __restrict__ Wq,
                            const float* __restrict__ bq,
                            const float* __restrict__ Wv,
                            const float* __restrict__ bv) {
    __shared__ float part[4][64];
    __shared__ float se[64];
    __shared__ float As[64];
    const int c = blockIdx.x;
    const int b = blockIdx.y;
    const int d = threadIdx.x & 63;
    const int ic = threadIdx.x >> 6;

    const float* T2b = g_T2 + (size_t)b * 193 * 64;
    const int ibeg = ic * 48;
    float e = 0.0f;
#pragma unroll 4
    for (int k = 0; k < 48; k++)
        e += Wq[c * 192 + ibeg + k] * T2b[(ibeg + k) * 64 + d];
    if (ic == 3) e += bq[c] * T2b[192 * 64 + d];
    part[ic][d] = e;
    __syncthreads();

    if (threadIdx.x < 64)
        se[d] = (part[0][d] + part[1][d] + part[2][d] + part[3][d]) * 0.125f;
    __syncthreads();

    if (threadIdx.x < 64) {
        const float e0 = se[d];
        float mx = -1e30f;
#pragma unroll 4
        for (int k = 0; k < 64; k++) mx = fmaxf(mx, se[k]);
        float s = 0.0f;
#pragma unroll 4
        for (int k = 0; k < 64; k++) s += expf(se[k] - mx);
        As[d] = expf(e0 - mx) / s;
    }
    __syncthreads();

    const int j = threadIdx.x;
    if (j < JT) {
        float m = 0.0f;
        if (j < 192) {
#pragma unroll 4
            for (int dd = 0; dd < 64; dd++) m += As[dd] * Wv[dd * 192 + j];
        } else if (j == 192) {
#pragma unroll 4
            for (int dd = 0; dd < 64; dd++) m += As[dd] * bv[dd];
        }
        unsigned short h, lo;
        split_bf16(m, h, lo);
        g_Mhi[(size_t)(b * 64 + c) * JT + j] = h;
        g_Mlo[(size_t)(b * 64 + c) * JT + j] = lo;
    }
}

// ---------------------------------------------------------------------------
// kernel 5: out[b] = M X_aug  (64ch x 128px tiles) — round-6 version
// ---------------------------------------------------------------------------
#define OUT_SMEM (2 * 64 * ASTR * 2 + 2 * 64 * OXS * 2)

__global__ __launch_bounds__(256, 2)
void cam_out_mma(const float* __restrict__ rgb,
                 const float* __restrict__ hsv,
                 const float* __restrict__ lab,
                 float* __restrict__ out) {
    extern __shared__ __align__(16) __nv_bfloat16 osm[];
    __nv_bfloat16* Ahi = osm;                        // [64][216]
    __nv_bfloat16* Alo = Ahi + 64 * ASTR;
    __nv_bfloat16* Xhi = Alo + 64 * ASTR;            // [64][136]
    __nv_bfloat16* Xlo = Xhi + 64 * OXS;

    const int tid = threadIdx.x;
    const int l = tid & 31;
    const int w = tid >> 5;
    const int wm = w >> 2;
    const int wn = w & 3;
    const int b = blockIdx.y;
    const int px0 = blockIdx.x * OTN;

    const float* bases[3] = {
        rgb + (size_t)b * 64 * NPIX,
        hsv + (size_t)b * 64 * NPIX,
        lab + (size_t)b * 64 * NPIX
    };

    const uint32_t* mhi = (const uint32_t*)(g_Mhi + (size_t)b * 64 * JT);
    const uint32_t* mlo = (const uint32_t*)(g_Mlo + (size_t)b * 64 * JT);
    for (int idx = tid; idx < 64 * 104; idx += 256) {
        const int c = idx / 104, kk = idx % 104;
        ((uint32_t*)(Ahi + c * ASTR))[kk] = mhi[c * 104 + kk];
        ((uint32_t*)(Alo + c * ASTR))[kk] = mlo[c * 104 + kk];
    }

    float acc[2][4][4];
#pragma unroll
    for (int mi = 0; mi < 2; mi++)
#pragma unroll
        for (int nt = 0; nt < 4; nt++)
#pragma unroll
            for (int q = 0; q < 4; q++) acc[mi][nt][q] = 0.0f;

    const uint32_t xhiB = smem_u32(Xhi);
    const uint32_t xloB = smem_u32(Xlo);

    for (int kc = 0; kc < JT; kc += 64) {
        const int klen = (kc + 64 <= JT) ? 64 : (JT - kc);
        __syncthreads();
        for (int idx = tid; idx < klen * 64; idx += 256) {
            const int kr = idx >> 6;
            const int pq = idx & 63;
            const int ch = kc + kr;
            float2 v;
            if (ch < 192)
                v = *(const float2*)(bases[ch >> 6] + (size_t)(ch & 63) * NPIX +
                                     px0 + pq * 2);
            else if (ch == 192)
                v = make_float2(1.0f, 1.0f);
            else
                v = make_float2(0.0f, 0.0f);
            unsigned short h0, l0, h1, l1;
            split_bf16(v.x, h0, l0);
            split_bf16(v.y, h1, l1);
            ((uint32_t*)(Xhi + kr * OXS))[pq] = (uint32_t)h0 | ((uint32_t)h1 << 16);
            ((uint32_t*)(Xlo + kr * OXS))[pq] = (uint32_t)l0 | ((uint32_t)l1 << 16);
        }
        __syncthreads();

        const int nks = klen / 16;
#pragma unroll 1
        for (int ks = 0; ks < nks; ks++) {
            uint32_t AH[2][4], AL[2][4];
#pragma unroll
            for (int mi = 0; mi < 2; mi++) {
                const int arow = (wm * 2 + mi) * 16 + (l >> 2);
                const uint32_t* ph = (const uint32_t*)(Ahi + arow * ASTR + kc + ks * 16);
                const uint32_t* ph8 = ph + 8 * (ASTR / 2);
                AH[mi][0] = ph[l & 3];  AH[mi][2] = ph[(l & 3) + 4];
                AH[mi][1] = ph8[l & 3]; AH[mi][3] = ph8[(l & 3) + 4];
                const uint32_t* ql = (const uint32_t*)(Alo + arow * ASTR + kc + ks * 16);
                const uint32_t* ql8 = ql + 8 * (ASTR / 2);
                AL[mi][0] = ql[l & 3];  AL[mi][2] = ql[(l & 3) + 4];
                AL[mi][1] = ql8[l & 3]; AL[mi][3] = ql8[(l & 3) + 4];
            }
            const uint32_t rowoff = (uint32_t)(ks * 16 + (l & 15)) * (OXS * 2);
#pragma unroll
            for (int nt = 0; nt < 4; nt++) {
                const uint32_t coloff = (uint32_t)(wn * 32 + nt * 8) * 2;
                uint32_t bh0, bh1, bl0, bl1;
                LDSM_X2_T(bh0, bh1, xhiB + rowoff + coloff);
                LDSM_X2_T(bl0, bl1, xloB + rowoff + coloff);
#pragma unroll
                for (int mi = 0; mi < 2; mi++) {
                    MMA16816(acc[mi][nt], AH[mi][0], AH[mi][1], AH[mi][2], AH[mi][3], bh0, bh1);
                    MMA16816(acc[mi][nt], AH[mi][0], AH[mi][1], AH[mi][2], AH[mi][3], bl0, bl1);
                    MMA16816(acc[mi][nt], AL[mi][0], AL[mi][1], AL[mi][2], AL[mi][3], bh0, bh1);
                }
            }
        }
    }

#pragma unroll
    for (int mi = 0; mi < 2; mi++) {
        const int c0 = (wm * 2 + mi) * 16 + (l >> 2);
#pragma unroll
        for (int nt = 0; nt < 4; nt++) {
            const int px = px0 + wn * 32 + nt * 8 + 2 * (l & 3);
            float* op = out + (size_t)(b * 64 + c0) * NPIX + px;
            *(float2*)op = make_float2(acc[mi][nt][0], acc[mi][nt][1]);
            *(float2*)(op + 8 * NPIX) = make_float2(acc[mi][nt][2], acc[mi][nt][3]);
        }
    }
}

// ---------------------------------------------------------------------------
// launch — 3 nops keep cam_gram_mma in profiled slot #4
// ---------------------------------------------------------------------------
extern "C" void kernel_launch(void* const* d_in, const int* in_sizes, int n_in,
                              void* d_out, int out_size) {
    const float* rgb = (const float*)d_in[0];
    const float* hsv = (const float*)d_in[1];
    const float* lab = (const float*)d_in[2];
    const float* Wq  = (const float*)d_in[3];
    const float* bq  = (const float*)d_in[4];
    const float* Wk  = (const float*)d_in[5];
    const float* bk  = (const float*)d_in[6];
    const float* Wv  = (const float*)d_in[7];
    const float* bv  = (const float*)d_in[8];
    float* out = (float*)d_out;

    cudaFuncSetAttribute(cam_gram_mma, cudaFuncAttributeMaxDynamicSharedMemorySize, GRAM_SMEM);
    cudaFuncSetAttribute(cam_out_mma, cudaFuncAttributeMaxDynamicSharedMemorySize, OUT_SMEM);

    cam_nop<<<1, 32>>>();
    cam_nop<<<1, 32>>>();
    cam_nop<<<1, 32>>>();
    cam_gram_mma<<<dim3(SPLITS, 4, 2), 512, GRAM_SMEM>>>(rgb, hsv, lab);
    cam_reduceG<<<(4 * JT * JT) / 256, 256>>>();
    cam_projT2<<<dim3(49, 4), 256>>>(Wk, bk);
    cam_energyM<<<dim3(64, 4), 256>>>(Wq, bq, Wv, bv);
    cam_out_mma<<<dim3(NPIX / OTN, 4), 256, OUT_SMEM>>>(rgb, hsv, lab, out);
}

// round 12
// speedup vs baseline: 1.2159x; 1.2159x over previous
#include <cuda_runtime.h>
#include <cuda_bf16.h>
#include <cstdint>

// ============================================================================
// CAM via Gram restructuring, mma.sync bf16 hi/lo.
// R12: global bf16 hi/lo pre-split; gram/out stage via pure 16B copies.
// ============================================================================

#define NPIX   65536
#define JT     208
#define SPLITS 37
#define GCH    128    // gram pixels per chunk
#define GSTR   136    // gram smem row stride (bf16) -> 272B = 17 uint4
#define ASTR   216    // out A smem stride (bf16)
#define OXS    136    // out X smem stride (bf16) -> 272B = 17 uint4
#define OTN    128    // out pixels per CTA

__device__ unsigned short g_Xhi[4 * 192 * NPIX];   // bf16 hi plane
__device__ unsigned short g_Xlo[4 * 192 * NPIX];   // bf16 lo plane
__device__ float g_Gp[4 * SPLITS * JT * JT];
__device__ float g_G[4 * JT * JT];
__device__ float g_T2[4 * 193 * 64];
__device__ unsigned short g_Mhi[4 * 64 * JT];
__device__ unsigned short g_Mlo[4 * 64 * JT];

// ---------------------------------------------------------------------------
static __device__ __forceinline__ uint32_t smem_u32(const void* p) {
    uint32_t a;
    asm("{ .reg .u64 t; cvta.to.shared.u64 t, %1; cvt.u32.u64 %0, t; }"
        : "=r"(a) : "l"(p));
    return a;
}

#define MMA16816(d, a0, a1, a2, a3, b0, b1) \
    asm volatile("mma.sync.aligned.m16n8k16.row.col.f32.bf16.bf16.f32 " \
        "{%0,%1,%2,%3}, {%4,%5,%6,%7}, {%8,%9}, {%0,%1,%2,%3};" \
        : "+f"((d)[0]), "+f"((d)[1]), "+f"((d)[2]), "+f"((d)[3]) \
        : "r"(a0), "r"(a1), "r"(a2), "r"(a3), "r"(b0), "r"(b1))

#define LDSM_X2_T(r0, r1, addr) \
    asm volatile("ldmatrix.sync.aligned.m8n8.x2.trans.shared.b16 {%0,%1}, [%2];" \
        : "=r"(r0), "=r"(r1) : "r"(addr))

static __device__ __forceinline__ void split_bf16(float x, unsigned short& h,
                                                  unsigned short& lo) {
    __nv_bfloat16 hb = __float2bfloat16(x);
    __nv_bfloat16 lb = __float2bfloat16(x - __bfloat162float(hb));
    h = __bfloat16_as_ushort(hb);
    lo = __bfloat16_as_ushort(lb);
}

__global__ void cam_nop() {}

// ---------------------------------------------------------------------------
// kernel 0: pre-split X -> global bf16 hi/lo planes (DRAM-bound)
// grid (6144, 4) x 256 threads; 8 px per thread
// ---------------------------------------------------------------------------
__global__ __launch_bounds__(256)
void cam_presplit(const float* __restrict__ rgb,
                  const float* __restrict__ hsv,
                  const float* __restrict__ lab) {
    const int b = blockIdx.y;
    const int u = blockIdx.x * 256 + threadIdx.x;
    const int px8 = u * 8;
    const int ch = px8 >> 16;
    const int px = px8 & 65535;

    const float* bases[3] = {
        rgb + (size_t)b * 64 * NPIX,
        hsv + (size_t)b * 64 * NPIX,
        lab + (size_t)b * 64 * NPIX
    };
    const float* src = bases[ch >> 6] + (size_t)(ch & 63) * NPIX + px;

    const float4 v0 = *(const float4*)src;
    const float4 v1 = *(const float4*)(src + 4);

    unsigned short h[8], l[8];
    split_bf16(v0.x, h[0], l[0]); split_bf16(v0.y, h[1], l[1]);
    split_bf16(v0.z, h[2], l[2]); split_bf16(v0.w, h[3], l[3]);
    split_bf16(v1.x, h[4], l[4]); split_bf16(v1.y, h[5], l[5]);
    split_bf16(v1.z, h[6], l[6]); split_bf16(v1.w, h[7], l[7]);

    uint4 hv, lv;
    hv.x = (uint32_t)h[0] | ((uint32_t)h[1] << 16);
    hv.y = (uint32_t)h[2] | ((uint32_t)h[3] << 16);
    hv.z = (uint32_t)h[4] | ((uint32_t)h[5] << 16);
    hv.w = (uint32_t)h[6] | ((uint32_t)h[7] << 16);
    lv.x = (uint32_t)l[0] | ((uint32_t)l[1] << 16);
    lv.y = (uint32_t)l[2] | ((uint32_t)l[3] << 16);
    lv.z = (uint32_t)l[4] | ((uint32_t)l[5] << 16);
    lv.w = (uint32_t)l[6] | ((uint32_t)l[7] << 16);

    const size_t off = ((size_t)(b * 192 + ch) << 16) + px;
    *(uint4*)(g_Xhi + off) = hv;
    *(uint4*)(g_Xlo + off) = lv;
}

// ---------------------------------------------------------------------------
// kernel 1: split-K Gram, tiles halved across blockIdx.z, 2 CTAs/SM.
// Staging = pure 16B copies from pre-split planes.
// ---------------------------------------------------------------------------
#define GRAM_SMEM (2 * JT * GSTR * 2)

__global__ __launch_bounds__(512, 2)
void cam_gram_mma() {
    extern __shared__ __align__(16) __nv_bfloat16 gsm[];
    __nv_bfloat16* hiP = gsm;                 // [208][136]
    __nv_bfloat16* loP = gsm + JT * GSTR;

    const int tid = threadIdx.x;
    const int l = tid & 31;
    const int w = tid >> 5;       // 0..15
    const int split = blockIdx.x;
    const int b = blockIdx.y;
    const int z = blockIdx.z;     // tile half

    // static rows 192..207 (row 192 hi = 1.0, else 0)
    for (int idx = tid; idx < 2 * 16 * 64; idx += 512) {
        const int pl = idx >> 10;
        const int r = (idx >> 6) & 15;
        const int q = idx & 63;
        uint32_t* p = (uint32_t*)((pl ? loP : hiP) + (192 + r) * GSTR);
        p[q] = (pl == 0 && r == 0) ? 0x3F803F80u : 0u;
    }

    // tiles [z*91, z*91+91): per warp 6 (w<11) or 5 (w>=11)
    const int startL = (w < 11) ? 6 * w : 66 + 5 * (w - 11);
    const int cnt = (w < 11) ? 6 : 5;
    const int start = z * 91 + startL;
    int mtA[6], ntA[6];
    {
        int rem = start, mt = 0;
        while (mt < 13 && rem >= 26 - 2 * mt) { rem -= 26 - 2 * mt; mt++; }
        int nt = 2 * mt + rem;
#pragma unroll
        for (int t = 0; t < 6; t++) {
            if (mt >= 13) { mt = 12; nt = 25; }
            mtA[t] = mt; ntA[t] = nt;
            nt++;
            if (nt >= 26) { mt++; nt = 2 * mt; }
        }
    }

    float acc[6][4];
#pragma unroll
    for (int t = 0; t < 6; t++)
#pragma unroll
        for (int q = 0; q < 4; q++) acc[t][q] = 0.0f;

    for (int chunk = split; chunk < NPIX / GCH; chunk += SPLITS) {
        const int n0 = chunk * GCH;
        __syncthreads();
        // stage rows 0..191: 16B copies from pre-split planes (12 iters/thread)
        for (int u2 = tid; u2 < 192 * 16 * 2; u2 += 512) {
            const int plane = (u2 >= 3072) ? 1 : 0;
            const int uu = plane ? (u2 - 3072) : u2;
            const int j = uu >> 4;
            const int q = uu & 15;
            const unsigned short* srcp = (plane ? g_Xlo : g_Xhi) +
                (((size_t)(b * 192 + j)) << 16) + n0 + q * 8;
            *((uint4*)((plane ? loP : hiP) + j * GSTR) + q) = *(const uint4*)srcp;
        }
        __syncthreads();

#pragma unroll 1
        for (int ks = 0; ks < GCH / 16; ks++) {
            int prev = -1;
            uint32_t ah0 = 0, ah1 = 0, ah2 = 0, ah3 = 0;
            uint32_t al0 = 0, al1 = 0, al2 = 0, al3 = 0;
#pragma unroll
            for (int t = 0; t < 6; t++) {
                if (t < cnt) {
                    const int mt = mtA[t];
                    const int nt = ntA[t];
                    if (mt != prev) {
                        prev = mt;
                        const int arow = mt * 16 + (l >> 2);
                        const uint32_t* ph = (const uint32_t*)(hiP + arow * GSTR + ks * 16);
                        const uint32_t* ph8 = ph + 8 * (GSTR / 2);
                        ah0 = ph[l & 3];  ah2 = ph[(l & 3) + 4];
                        ah1 = ph8[l & 3]; ah3 = ph8[(l & 3) + 4];
                        const uint32_t* ql = (const uint32_t*)(loP + arow * GSTR + ks * 16);
                        const uint32_t* ql8 = ql + 8 * (GSTR / 2);
                        al0 = ql[l & 3];  al2 = ql[(l & 3) + 4];
                        al1 = ql8[l & 3]; al3 = ql8[(l & 3) + 4];
                    }
                    const int brow = nt * 8 + (l >> 2);
                    const uint32_t* pb = (const uint32_t*)(hiP + brow * GSTR + ks * 16);
                    const uint32_t bh0 = pb[l & 3], bh1 = pb[(l & 3) + 4];
                    const uint32_t* pbl = (const uint32_t*)(loP + brow * GSTR + ks * 16);
                    const uint32_t bl0 = pbl[l & 3], bl1 = pbl[(l & 3) + 4];
                    MMA16816(acc[t], ah0, ah1, ah2, ah3, bh0, bh1);
                    MMA16816(acc[t], ah0, ah1, ah2, ah3, bl0, bl1);
                    MMA16816(acc[t], al0, al1, al2, al3, bh0, bh1);
                }
            }
        }
    }

    float* gp = g_Gp + (size_t)(b * SPLITS + split) * JT * JT;
#pragma unroll
    for (int t = 0; t < 6; t++) {
        if (t < cnt) {
            const int i0 = mtA[t] * 16 + (l >> 2);
            const int j0 = ntA[t] * 8 + 2 * (l & 3);
            *(float2*)&gp[(size_t)i0 * JT + j0] = make_float2(acc[t][0], acc[t][1]);
            *(float2*)&gp[(size_t)(i0 + 8) * JT + j0] = make_float2(acc[t][2], acc[t][3]);
        }
    }
}

// ---------------------------------------------------------------------------
// kernel 2: reduce split-K + mirror
// ---------------------------------------------------------------------------
__global__ void cam_reduceG() {
    const int idx = blockIdx.x * 256 + threadIdx.x;
    const int b = idx / (JT * JT);
    const int rc = idx % (JT * JT);
    const int i = rc / JT, j = rc % JT;
    if (i > j) return;
    const float* gp = g_Gp + (size_t)b * SPLITS * JT * JT + rc;
    float acc = 0.0f;
#pragma unroll 4
    for (int s = 0; s < SPLITS; s++) acc += gp[(size_t)s * JT * JT];
    float* G = g_G + (size_t)b * JT * JT;
    G[i * JT + j] = acc;
    G[j * JT + i] = acc;
}

// ---------------------------------------------------------------------------
// kernel 3: T2[b][i][d] = sum_j G[b][i][j] Wk_aug[d][j]
// ---------------------------------------------------------------------------
__global__ void cam_projT2(const float* __restrict__ Wk,
                           const float* __restrict__ bk) {
    __shared__ float Gs[4][200];
    const int b = blockIdx.y;
    const int i0 = blockIdx.x * 4;
    const int tid = threadIdx.x;

    for (int idx = tid; idx < 4 * 193; idx += 256) {
        const int ii = idx / 193, j = idx % 193;
        if (i0 + ii < 193)
            Gs[ii][j] = g_G[(size_t)b * JT * JT + (size_t)(i0 + ii) * JT + j];
    }
    __syncthreads();

    const int d = tid & 63;
    const int ii = tid >> 6;
    const int i = i0 + ii;
    if (i < 193) {
        float acc = 0.0f;
#pragma unroll 4
        for (int j = 0; j < 192; j++) acc += Wk[d * 192 + j] * Gs[ii][j];
        acc += bk[d] * Gs[ii][192];
        g_T2[(size_t)b * 193 * 64 + i * 64 + d] = acc;
    }
}

// ---------------------------------------------------------------------------
// kernel 4: energy + softmax + M row, fused  (grid (64,4), 256 threads)
// ---------------------------------------------------------------------------
__global__ void cam_energyM(const float* __restrict__ Wq,
                            const float* __restrict__ bq,
                            const float* __restrict__ Wv,
                            const float* __restrict__ bv) {
    __shared__ float part[4][64];
    __shared__ float se[64];
    __shared__ float As[64];
    const int c = blockIdx.x;
    const int b = blockIdx.y;
    const int d = threadIdx.x & 63;
    const int ic = threadIdx.x >> 6;

    const float* T2b = g_T2 + (size_t)b * 193 * 64;
    const int ibeg = ic * 48;
    float e = 0.0f;
#pragma unroll 4
    for (int k = 0; k < 48; k++)
        e += Wq[c * 192 + ibeg + k] * T2b[(ibeg + k) * 64 + d];
    if (ic == 3) e += bq[c] * T2b[192 * 64 + d];
    part[ic][d] = e;
    __syncthreads();

    if (threadIdx.x < 64)
        se[d] = (part[0][d] + part[1][d] + part[2][d] + part[3][d]) * 0.125f;
    __syncthreads();

    if (threadIdx.x < 64) {
        const float e0 = se[d];
        float mx = -1e30f;
#pragma unroll 4
        for (int k = 0; k < 64; k++) mx = fmaxf(mx, se[k]);
        float s = 0.0f;
#pragma unroll 4
        for (int k = 0; k < 64; k++) s += expf(se[k] - mx);
        As[d] = expf(e0 - mx) / s;
    }
    __syncthreads();

    const int j = threadIdx.x;
    if (j < JT) {
        float m = 0.0f;
        if (j < 192) {
#pragma unroll 4
            for (int dd = 0; dd < 64; dd++) m += As[dd] * Wv[dd * 192 + j];
        } else if (j == 192) {
#pragma unroll 4
            for (int dd = 0; dd < 64; dd++) m += As[dd] * bv[dd];
        }
        unsigned short h, lo;
        split_bf16(m, h, lo);
        g_Mhi[(size_t)(b * 64 + c) * JT + j] = h;
        g_Mlo[(size_t)(b * 64 + c) * JT + j] = lo;
    }
}

// ---------------------------------------------------------------------------
// kernel 5: out[b] = M X_aug  (64ch x 128px tiles); staging = 16B copies
// ---------------------------------------------------------------------------
#define OUT_SMEM (2 * 64 * ASTR * 2 + 2 * 64 * OXS * 2)

__global__ __launch_bounds__(256, 2)
void cam_out_mma(float* __restrict__ out) {
    extern __shared__ __align__(16) __nv_bfloat16 osm[];
    __nv_bfloat16* Ahi = osm;                        // [64][216]
    __nv_bfloat16* Alo = Ahi + 64 * ASTR;
    __nv_bfloat16* Xhi = Alo + 64 * ASTR;            // [64][136]
    __nv_bfloat16* Xlo = Xhi + 64 * OXS;

    const int tid = threadIdx.x;
    const int l = tid & 31;
    const int w = tid >> 5;
    const int wm = w >> 2;
    const int wn = w & 3;
    const int b = blockIdx.y;
    const int px0 = blockIdx.x * OTN;

    const uint32_t* mhi = (const uint32_t*)(g_Mhi + (size_t)b * 64 * JT);
    const uint32_t* mlo = (const uint32_t*)(g_Mlo + (size_t)b * 64 * JT);
    for (int idx = tid; idx < 64 * 104; idx += 256) {
        const int c = idx / 104, kk = idx % 104;
        ((uint32_t*)(Ahi + c * ASTR))[kk] = mhi[c * 104 + kk];
        ((uint32_t*)(Alo + c * ASTR))[kk] = mlo[c * 104 + kk];
    }

    float acc[2][4][4];
#pragma unroll
    for (int mi = 0; mi < 2; mi++)
#pragma unroll
        for (int nt = 0; nt < 4; nt++)
#pragma unroll
            for (int q = 0; q < 4; q++) acc[mi][nt][q] = 0.0f;

    const uint32_t xhiB = smem_u32(Xhi);
    const uint32_t xloB = smem_u32(Xlo);

    for (int kc = 0; kc < JT; kc += 64) {
        const int klen = (kc + 64 <= JT) ? 64 : (JT - kc);
        __syncthreads();
        if (kc < 192) {
            // 16B copies from pre-split planes (8 iters/thread)
            for (int u2 = tid; u2 < klen * 16 * 2; u2 += 256) {
                const int plane = (u2 >= klen * 16) ? 1 : 0;
                const int uu = plane ? (u2 - klen * 16) : u2;
                const int kr = uu >> 4;
                const int q = uu & 15;
                const unsigned short* srcp = (plane ? g_Xlo : g_Xhi) +
                    (((size_t)(b * 192 + kc + kr)) << 16) + px0 + q * 8;
                *((uint4*)((plane ? Xlo : Xhi) + kr * OXS) + q) = *(const uint4*)srcp;
            }
        } else {
            // rows 192..207: hi row 0 (ch 192) = ones, everything else zero
            for (int u2 = tid; u2 < 16 * 16 * 2; u2 += 256) {
                const int plane = (u2 >= 256) ? 1 : 0;
                const int uu = plane ? (u2 - 256) : u2;
                const int kr = uu >> 4;
                const int q = uu & 15;
                const uint4 val = (plane == 0 && kr == 0)
                    ? make_uint4(0x3F803F80u, 0x3F803F80u, 0x3F803F80u, 0x3F803F80u)
                    : make_uint4(0u, 0u, 0u, 0u);
                *((uint4*)((plane ? Xlo : Xhi) + kr * OXS) + q) = val;
            }
        }
        __syncthreads();

        const int nks = klen / 16;
#pragma unroll 1
        for (int ks = 0; ks < nks; ks++) {
            uint32_t AH[2][4], AL[2][4];
#pragma unroll
            for (int mi = 0; mi < 2; mi++) {
                const int arow = (wm * 2 + mi) * 16 + (l >> 2);
                const uint32_t* ph = (const uint32_t*)(Ahi + arow * ASTR + kc + ks * 16);
                const uint32_t* ph8 = ph + 8 * (ASTR / 2);
                AH[mi][0] = ph[l & 3];  AH[mi][2] = ph[(l & 3) + 4];
                AH[mi][1] = ph8[l & 3]; AH[mi][3] = ph8[(l & 3) + 4];
                const uint32_t* ql = (const uint32_t*)(Alo + arow * ASTR + kc + ks * 16);
                const uint32_t* ql8 = ql + 8 * (ASTR / 2);
                AL[mi][0] = ql[l & 3];  AL[mi][2] = ql[(l & 3) + 4];
                AL[mi][1] = ql8[l & 3]; AL[mi][3] = ql8[(l & 3) + 4];
            }
            const uint32_t rowoff = (uint32_t)(ks * 16 + (l & 15)) * (OXS * 2);
#pragma unroll
            for (int nt = 0; nt < 4; nt++) {
                const uint32_t coloff = (uint32_t)(wn * 32 + nt * 8) * 2;
                uint32_t bh0, bh1, bl0, bl1;
                LDSM_X2_T(bh0, bh1, xhiB + rowoff + coloff);
                LDSM_X2_T(bl0, bl1, xloB + rowoff + coloff);
#pragma unroll
                for (int mi = 0; mi < 2; mi++) {
                    MMA16816(acc[mi][nt], AH[mi][0], AH[mi][1], AH[mi][2], AH[mi][3], bh0, bh1);
                    MMA16816(acc[mi][nt], AH[mi][0], AH[mi][1], AH[mi][2], AH[mi][3], bl0, bl1);
                    MMA16816(acc[mi][nt], AL[mi][0], AL[mi][1], AL[mi][2], AL[mi][3], bh0, bh1);
                }
            }
        }
    }

#pragma unroll
    for (int mi = 0; mi < 2; mi++) {
        const int c0 = (wm * 2 + mi) * 16 + (l >> 2);
#pragma unroll
        for (int nt = 0; nt < 4; nt++) {
            const int px = px0 + wn * 32 + nt * 8 + 2 * (l & 3);
            float* op = out + (size_t)(b * 64 + c0) * NPIX + px;
            *(float2*)op = make_float2(acc[mi][nt][0], acc[mi][nt][1]);
            *(float2*)(op + 8 * NPIX) = make_float2(acc[mi][nt][2], acc[mi][nt][3]);
        }
    }
}

// ---------------------------------------------------------------------------
// launch — presplit + 2 nops keep cam_gram_mma in profiled slot #4
// ---------------------------------------------------------------------------
extern "C" void kernel_launch(void* const* d_in, const int* in_sizes, int n_in,
                              void* d_out, int out_size) {
    const float* rgb = (const float*)d_in[0];
    const float* hsv = (const float*)d_in[1];
    const float* lab = (const float*)d_in[2];
    const float* Wq  = (const float*)d_in[3];
    const float* bq  = (const float*)d_in[4];
    const float* Wk  = (const float*)d_in[5];
    const float* bk  = (const float*)d_in[6];
    const float* Wv  = (const float*)d_in[7];
    const float* bv  = (const float*)d_in[8];
    float* out = (float*)d_out;

    cudaFuncSetAttribute(cam_gram_mma, cudaFuncAttributeMaxDynamicSharedMemorySize, GRAM_SMEM);
    cudaFuncSetAttribute(cam_out_mma, cudaFuncAttributeMaxDynamicSharedMemorySize, OUT_SMEM);

    cam_presplit<<<dim3(6144, 4), 256>>>(rgb, hsv, lab);
    cam_nop<<<1, 32>>>();
    cam_nop<<<1, 32>>>();
    cam_gram_mma<<<dim3(SPLITS, 4, 2), 512, GRAM_SMEM>>>();
    cam_reduceG<<<(4 * JT * JT) / 256, 256>>>();
    cam_projT2<<<dim3(49, 4), 256>>>(Wk, bk);
    cam_energyM<<<dim3(64, 4), 256>>>(Wq, bq, Wv, bv);
    cam_out_mma<<<dim3(NPIX / OTN, 4), 256, OUT_SMEM>>>(out);
}